// round 16
// baseline (speedup 1.0000x reference)
#include <cuda_runtime.h>
#include <cstdint>

#define NRES 128
#define TT 8   // frames (fixed by problem shape)
#define PPB 2  // tile-pairs per pair-role block (single-wave packing)

// ---------------- device-global scratch (zero-initialized at load; the
// finalizer block restores the all-zero invariant every call) ----------------
__device__ float        g_struct_pf[64];
__device__ double       g_lddt_score;
__device__ double       g_lddt_cnt;
__device__ double       g_bond_num;
__device__ double       g_bond_den;
__device__ float        g_res_sum[8 * NRES];
__device__ float        g_res_cnt[8 * NRES];
__device__ unsigned int g_done;

// ---------------- helpers ----------------
__device__ __forceinline__ float fsqrt_approx(float x) {
    float r;
    asm("sqrt.approx.f32 %0, %1;" : "=f"(r) : "f"(x));
    return r;
}

// packed f32x2 ops (sm_103a)
#define ADD2(o, a, b)    asm("add.rn.f32x2 %0, %1, %2;"      : "=l"(o) : "l"(a), "l"(b))
#define MUL2(o, a, b)    asm("mul.rn.f32x2 %0, %1, %2;"      : "=l"(o) : "l"(a), "l"(b))
#define FMA2(o, a, b, c) asm("fma.rn.f32x2 %0, %1, %2, %3;"  : "=l"(o) : "l"(a), "l"(b), "l"(c))
#define PACK2(o, lo, hi)   asm("mov.b64 %0, {%1, %2};"       : "=l"(o) : "f"(lo), "f"(hi))
#define UNPACK2(lo, hi, v) asm("mov.b64 {%0, %1}, %2;"       : "=f"(lo), "=f"(hi) : "l"(v))

// write-side publication: no acquire, no L1 invalidation
__device__ __forceinline__ void red_release_add(unsigned int* p, unsigned int v) {
    asm volatile("red.release.gpu.global.add.u32 [%0], %1;" :: "l"(p), "r"(v) : "memory");
}
__device__ __forceinline__ unsigned int ldcg_u32(const unsigned int* p) {
    unsigned int v;
    asm volatile("ld.global.cg.u32 %0, [%1];" : "=r"(v) : "l"(p) : "memory");
    return v;
}

// lDDT rational coefficients: with x=e^diff, b_k=e^{-th_k} (th = .5,1,2,4):
//   sum_k 1/(1+b_k x) = num(x)/den(x);  den = 1+E1x+E2x^2+E3x^3+E4x^4,
//   num = 4 + 3E1 x + 2E2 x^2 + E3 x^3
#define C_E1 1.1280610230f
#define C_E2 0.3753279228f
#define C_E3 0.0366994759f
#define C_E4 5.5308437e-4f
#define C_N1 3.3841830690f
#define C_N2 0.7506558456f

// swizzled slot for atom a: 5*(a>>2)+(a&3); 5*jg mod 8 is a permutation -> conflict-free
__device__ __forceinline__ int pidx(int a) { return 5 * (a >> 2) + (a & 3); }

__device__ __forceinline__ float blockReduceSum(float v) {
    __shared__ float sh[32];
    int lane = threadIdx.x & 31, wid = threadIdx.x >> 5;
#pragma unroll
    for (int o = 16; o; o >>= 1) v += __shfl_xor_sync(0xffffffffu, v, o);
    __syncthreads();
    if (lane == 0) sh[wid] = v;
    __syncthreads();
    int nw = (blockDim.x + 31) >> 5;
    v = (lane < nw) ? sh[lane] : 0.f;
#pragma unroll
    for (int o = 16; o; o >>= 1) v += __shfl_xor_sync(0xffffffffu, v, o);
    return v;
}

// ---------------- single kernel: pair + struct + bond workers + polling finalizer ----------------
__global__ void __launch_bounds__(256, 5)
mega_kernel(const float* __restrict__ xp, const float* __restrict__ xg,
            const float* __restrict__ sigma,
            const int* __restrict__ cond,
            const int* __restrict__ am, const int* __restrict__ om,
            const int* __restrict__ mol, const int* __restrict__ resid,
            const float* __restrict__ blen, const int* __restrict__ bidx,
            const int* __restrict__ bmask,
            float* __restrict__ out,
            int B, int T, int M, int NB,
            int ntiles, int tilepairs, int pairBlocksPerB, int nPair, int nStruct, int nWorkers) {
    int blk = blockIdx.x;
    int tid = threadIdx.x;

    if (blk < nPair) {
        // ================= pair role: PPB sequential 32x32 atom tiles =================
        __shared__ ulonglong2          sAi[TT][40], sAj[TT][40];
        __shared__ unsigned long long  sBi[TT][40], sBj[TT][40];
        __shared__ float  s_tf[TT], s_fw[TT];
        __shared__ int    s_ri[32], s_rj[32];
        __shared__ float  s_vi[32], s_vj[32];
        __shared__ float  s_W;

        int b  = blk / pairBlocksPerB;
        int ph = blk % pairBlocksPerB;

        // per-batch frame weights: staged once (same for both reps)
        if (tid == 0) {
            float s = 0.f;
            for (int t = 0; t < TT; t++) {
                float tf = cond[b * TT + t] ? 0.f : 1.f;
                s_tf[t] = tf; s += tf;
            }
            float denom = fmaxf(s, 1.f);
            float W = 0.f;
            for (int t = 0; t < TT; t++) { float f = s_tf[t] / denom; s_fw[t] = f; W += f; }
            s_W = W;
        }

        float sc = 0.f, cn = 0.f;

#pragma unroll 1
        for (int rep = 0; rep < PPB; rep++) {
            int p = ph * PPB + rep;
            if (p >= tilepairs) break;
            int ti = 0, rem = p;
            while (rem >= ntiles - ti) { rem -= ntiles - ti; ti++; }
            int tj = ti + rem;

            __syncthreads();   // smem reuse barrier (rep>0) / aligns with s_tf publish (rep 0)

            for (int e = tid; e < TT * 32 * 3; e += 256) {
                int t = e / 96, r = e % 96, a = r / 3, d = r % 3;
                int gi = ti * 32 + a, gj = tj * 32 + a;
                long oi = (((long)(b * TT + t)) * M + gi) * 3 + d;
                long oj = (((long)(b * TT + t)) * M + gj) * 3 + d;
                int pa = pidx(a);
                float pi_ = xp[oi], gi_ = xg[oi];
                float pj_ = -xp[oj], gj_ = -xg[oj];
                if (d < 2) {
                    ((float*)&sAi[t][pa])[2 * d + 0] = pi_;
                    ((float*)&sAi[t][pa])[2 * d + 1] = gi_;
                    ((float*)&sAj[t][pa])[2 * d + 0] = pj_;
                    ((float*)&sAj[t][pa])[2 * d + 1] = gj_;
                } else {
                    ((float*)&sBi[t][pa])[0] = pi_;
                    ((float*)&sBi[t][pa])[1] = gi_;
                    ((float*)&sBj[t][pa])[0] = pj_;
                    ((float*)&sBj[t][pa])[1] = gj_;
                }
            }
            if (tid < 32) {
                int gi = ti * 32 + tid, gj = tj * 32 + tid;
                s_vi[tid] = (am[b * M + gi] && om[b * M + gi]) ? 1.f : 0.f;
                s_vj[tid] = (am[b * M + gj] && om[b * M + gj]) ? 1.f : 0.f;
                s_ri[tid] = resid[b * M + gi];
                s_rj[tid] = resid[b * M + gj];
            }
            __syncthreads();

            int ii = tid >> 3, jg = tid & 7;
            int gi = ti * 32 + ii;
            float vi = s_vi[ii];
            int   ri = s_ri[ii];
            int   ip = pidx(ii);
            int   jb = 5 * jg;          // pidx(jg*4+k) = 5*jg + k

            float lokf[4];
            bool  same[4];
#pragma unroll
            for (int k = 0; k < 4; k++) {
                int jj = jg * 4 + k, gj = tj * 32 + jj;
                bool vp = (gi < gj) && (vi != 0.f) && (s_vj[jj] != 0.f);
                lokf[k] = vp ? 1.f : 0.f;
                same[k] = vp && (ri == s_rj[jj]);
            }

            // packed flex accumulators per rep
            unsigned long long e1a[4] = {0ull, 0ull, 0ull, 0ull};
            unsigned long long e2a[4] = {0ull, 0ull, 0ull, 0ull};

#pragma unroll
            for (int t = 0; t < TT; t++) {
                ulonglong2         Ai = sAi[t][ip];
                unsigned long long Bi = sBi[t][ip];
                float tf = s_tf[t], fw = s_fw[t];
                unsigned long long fw2; PACK2(fw2, fw, fw);
#pragma unroll
                for (int m = 0; m < 2; m++) {
                    float nn[2], ddn[2];
#pragma unroll
                    for (int q = 0; q < 2; q++) {
                        int k = 2 * m + q;
                        ulonglong2         Aj = sAj[t][jb + k];
                        unsigned long long Bj = sBj[t][jb + k];
                        unsigned long long dx, dy, dz, sq;
                        ADD2(dx, Ai.x, Aj.x);          // (dpx, dgx)
                        ADD2(dy, Ai.y, Aj.y);          // (dpy, dgy)
                        ADD2(dz, Bi,   Bj);            // (dpz, dgz)
                        MUL2(sq, dx, dx);
                        FMA2(sq, dy, dy, sq);
                        FMA2(sq, dz, dz, sq);          // (dp^2, dg^2), exact
                        float sqp, sqg; UNPACK2(sqp, sqg, sq);
                        float dp = fsqrt_approx(sqp);
                        float dg = fsqrt_approx(sqg);

                        float diff = fminf(fabsf(dp - dg), 12.5f);
                        float x = __expf(diff);
                        float den = fmaf(fmaf(fmaf(fmaf(C_E4, x, C_E3), x, C_E2), x, C_E1), x, 1.f);
                        float num = fmaf(fmaf(fmaf(C_E3, x, C_N2), x, C_N1), x, 4.f);
                        float ok  = (dg < 15.f) ? lokf[k] * tf : 0.f;
                        nn[q]  = num * ok;
                        ddn[q] = den;
                        cn += ok;

                        unsigned long long dd;
                        PACK2(dd, dp, dg);
                        FMA2(e1a[k], fw2, dd, e1a[k]);
                        FMA2(e2a[k], fw2, sq, e2a[k]);
                    }
                    float cross = fmaf(nn[1], ddn[0], nn[0] * ddn[1]);
                    sc += __fdividef(cross, ddn[0] * ddn[1]);
                }
            }

#pragma unroll
            for (int k = 0; k < 4; k++) {
                if (same[k]) {
                    float e1p, e1g, e2p, e2g;
                    UNPACK2(e1p, e1g, e1a[k]);
                    UNPACK2(e2p, e2g, e2a[k]);
                    float W = s_W;
                    float vp_ = fmaxf(e2p - e1p * e1p * (2.f - W), 0.f);
                    float vg_ = fmaxf(e2g - e1g * e1g * (2.f - W), 0.f);
                    float sp = fsqrt_approx(vp_ + 1e-8f);
                    float sg = fsqrt_approx(vg_ + 1e-8f);
                    float dq = (sp - sg) * (sp - sg);
                    int r = min(max(ri, 0), NRES - 1);
                    atomicAdd(&g_res_sum[b * NRES + r], dq);
                    atomicAdd(&g_res_cnt[b * NRES + r], 1.f);
                }
            }
        }

        float tsc = blockReduceSum(sc);
        float tcn = blockReduceSum(cn);
        if (tid == 0) {
            atomicAdd(&g_lddt_score, (double)tsc);
            atomicAdd(&g_lddt_cnt, (double)tcn);
        }
        // publish: release-red (write-side only; no L1 invalidate)
        __syncthreads();
        if (tid == 0) red_release_add(&g_done, 1u);
    } else if (blk < nPair + nStruct) {
        // ================= struct role: one block per (b,t); also counts valid atoms =================
        int bt = blk - nPair;
        int b = bt / T;
        const float* P = xp + (long)bt * M * 3;
        const float* G = xg + (long)bt * M * 3;
        float acc = 0.f, vcnt = 0.f;
        for (int m = tid; m < M; m += 256) {
            float d0 = P[m * 3 + 0] - G[m * 3 + 0];
            float d1 = P[m * 3 + 1] - G[m * 3 + 1];
            float d2 = P[m * 3 + 2] - G[m * 3 + 2];
            float sq = fmaf(d0, d0, fmaf(d1, d1, d2 * d2));
            bool v = am[b * M + m] && om[b * M + m];
            int mt = mol[b * M + m];
            float w = v ? ((mt == 0) ? 1.f : (mt == 3) ? 10.f : 5.f) : 0.f;
            acc += sq * w;
            vcnt += v ? 1.f : 0.f;
        }
        acc  = blockReduceSum(acc);
        vcnt = blockReduceSum(vcnt);
        if (tid == 0) __stcg(&g_struct_pf[bt], acc / fmaxf(vcnt, 1.f));   // L2 direct
        __syncthreads();
        if (tid == 0) red_release_add(&g_done, 1u);
    } else if (blk < nWorkers) {
        // ================= bond role: one thread per (b, bond, frame) =================
        int g = (blk - nPair - nStruct) * 256 + tid;
        float num = 0.f, den = 0.f;
        if (g < B * NB * T) {
            int b  = g / (NB * T);
            int r  = g % (NB * T);
            int nb = r / T;
            int t  = r % T;
            int bond = b * NB + nb;
            if (bmask[bond]) {
                float tf = cond[b * T + t] ? 0.f : 1.f;
                int i = bidx[bond * 2 + 0];
                int j = bidx[bond * 2 + 1];
                const float* base = xp + ((long)(b * T + t)) * M * 3;
                float d0 = base[i * 3 + 0] - base[j * 3 + 0];
                float d1 = base[i * 3 + 1] - base[j * 3 + 1];
                float d2 = base[i * 3 + 2] - base[j * 3 + 2];
                float pl = fsqrt_approx(fmaf(d0, d0, fmaf(d1, d1, d2 * d2)) + 1e-12f);
                float df = pl - blen[bond];
                num = df * df * tf;
                den = tf;
            }
        }
        num = blockReduceSum(num);
        den = blockReduceSum(den);
        if (tid == 0) {
            atomicAdd(&g_bond_num, (double)num);
            atomicAdd(&g_bond_den, (double)den);
        }
        __syncthreads();
        if (tid == 0) red_release_add(&g_done, 1u);
    } else {
        // ================= finalizer block: poll L2 counter, then reduce =================
        __shared__ unsigned int s_go;
        if (tid == 0) {
            while (ldcg_u32(&g_done) < (unsigned int)nWorkers) __nanosleep(64);
            s_go = 1u;
        }
        __syncthreads();
        (void)s_go;

        // all accumulator state is in L2 (atomics / st.cg); read via __ldcg
        float lsum = 0.f, lok2 = 0.f;
        for (int i = tid; i < B * NRES; i += 256) {
            float c = __ldcg(&g_res_cnt[i]);
            if (c > 0.f) { lsum += __ldcg(&g_res_sum[i]) / c; lok2 += 1.f; }
        }
        float t1 = blockReduceSum(lsum);
        float t2 = blockReduceSum(lok2);

        float ssum = 0.f, tfs = 0.f;
        for (int i = tid; i < B * T; i += 256) {
            float s = sigma[i];
            float tf = cond[i] ? 0.f : 1.f;
            tfs += tf;
            float den = s * 16.f + 1e-8f;
            float ew = (s * s + 256.f) / (den * den) * tf;
            ssum += ew * __ldcg(&g_struct_pf[i]);
        }
        float t3 = blockReduceSum(ssum);
        float t4 = blockReduceSum(tfs);

        if (tid == 0) {
            double lsc  = __longlong_as_double(__ldcg((const long long*)&g_lddt_score));
            double lcn  = __longlong_as_double(__ldcg((const long long*)&g_lddt_cnt));
            double bnum = __longlong_as_double(__ldcg((const long long*)&g_bond_num));
            double bden = __longlong_as_double(__ldcg((const long long*)&g_bond_den));
            float l_local  = t1 / fmaxf(t2, 1.f);
            float l_struct = t3 / fmaxf(t4, 1.f);
            float l_lddt = 1.f - (float)((lsc * 0.25) / (lcn > 1.0 ? lcn : 1.0));
            float l_bond = (float)(bnum / (bden > 1.0 ? bden : 1.0));
            out[0] = l_struct + l_bond + l_lddt + 4.f * l_local;
        }

        // restore all-zero invariant (kernel-completion boundary publishes to next call)
        __syncthreads();
        for (int i = tid; i < 8 * NRES; i += 256) { g_res_sum[i] = 0.f; g_res_cnt[i] = 0.f; }
        for (int i = tid; i < 64; i += 256)        { g_struct_pf[i] = 0.f; }
        if (tid == 0) {
            g_lddt_score = 0.0; g_lddt_cnt = 0.0;
            g_bond_num = 0.0;   g_bond_den = 0.0;
            g_done = 0u;
        }
    }
}

// ---------------- launch ----------------
extern "C" void kernel_launch(void* const* d_in, const int* in_sizes, int n_in,
                              void* d_out, int out_size) {
    const float* xp    = (const float*)d_in[0];
    const float* xg    = (const float*)d_in[1];
    const float* sigma = (const float*)d_in[2];
    const float* blen  = (const float*)d_in[3];
    const int*   cond  = (const int*)d_in[4];
    const int*   am    = (const int*)d_in[5];
    const int*   om    = (const int*)d_in[6];
    const int*   mol   = (const int*)d_in[7];
    const int*   resid = (const int*)d_in[8];
    const int*   bidx  = (const int*)d_in[9];
    const int*   bmask = (const int*)d_in[10];

    int BT = in_sizes[2];                 // B*T
    int M  = in_sizes[0] / (BT * 3);      // atoms
    int B  = in_sizes[5] / M;             // batch
    int T  = BT / B;                      // frames (== 8)
    int NB = in_sizes[10] / B;            // bonds

    int ntiles = M / 32;
    int tilepairs = ntiles * (ntiles + 1) / 2;
    int pairBlocksPerB = (tilepairs + PPB - 1) / PPB;
    int nPair    = B * pairBlocksPerB;
    int nStruct  = B * T;
    int nBond    = (B * NB * T + 255) / 256;
    int nWorkers = nPair + nStruct + nBond;
    mega_kernel<<<nWorkers + 1, 256>>>(
        xp, xg, sigma, cond, am, om, mol, resid, blen, bidx, bmask,
        (float*)d_out, B, T, M, NB, ntiles, tilepairs, pairBlocksPerB, nPair, nStruct, nWorkers);
}

// round 17
// speedup vs baseline: 1.1651x; 1.1651x over previous
#include <cuda_runtime.h>
#include <cstdint>

#define NRES 128
#define TT 8   // frames (fixed by problem shape)

// ---------------- device-global scratch (zero-initialized at load; the
// finalizer block restores the all-zero invariant every call) ----------------
__device__ float        g_struct_pf[64];
__device__ double       g_lddt_score;
__device__ double       g_lddt_cnt;
__device__ double       g_bond_num;
__device__ double       g_bond_den;
__device__ float        g_res_sum[8 * NRES];
__device__ float        g_res_cnt[8 * NRES];
__device__ unsigned int g_done;

// ---------------- helpers ----------------
__device__ __forceinline__ float fsqrt_approx(float x) {
    float r;
    asm("sqrt.approx.f32 %0, %1;" : "=f"(r) : "f"(x));
    return r;
}

// packed f32x2 ops (sm_103a)
#define ADD2(o, a, b)    asm("add.rn.f32x2 %0, %1, %2;"      : "=l"(o) : "l"(a), "l"(b))
#define MUL2(o, a, b)    asm("mul.rn.f32x2 %0, %1, %2;"      : "=l"(o) : "l"(a), "l"(b))
#define FMA2(o, a, b, c) asm("fma.rn.f32x2 %0, %1, %2, %3;"  : "=l"(o) : "l"(a), "l"(b), "l"(c))
#define PACK2(o, lo, hi)   asm("mov.b64 %0, {%1, %2};"       : "=l"(o) : "f"(lo), "f"(hi))
#define UNPACK2(lo, hi, v) asm("mov.b64 {%0, %1}, %2;"       : "=f"(lo), "=f"(hi) : "l"(v))

// write-side publication: no acquire, no L1 invalidation
__device__ __forceinline__ void red_release_add(unsigned int* p, unsigned int v) {
    asm volatile("red.release.gpu.global.add.u32 [%0], %1;" :: "l"(p), "r"(v) : "memory");
}
__device__ __forceinline__ unsigned int ldcg_u32(const unsigned int* p) {
    unsigned int v;
    asm volatile("ld.global.cg.u32 %0, [%1];" : "=r"(v) : "l"(p) : "memory");
    return v;
}

// lDDT rational coefficients: with x=e^diff, b_k=e^{-th_k} (th = .5,1,2,4):
//   sum_k 1/(1+b_k x) = num(x)/den(x);  den = 1+E1x+E2x^2+E3x^3+E4x^4,
//   num = 4 + 3E1 x + 2E2 x^2 + E3 x^3
#define C_E1 1.1280610230f
#define C_E2 0.3753279228f
#define C_E3 0.0366994759f
#define C_E4 5.5308437e-4f
#define C_N1 3.3841830690f
#define C_N2 0.7506558456f

// swizzled slot for atom a: 5*(a>>2)+(a&3); 5*jg mod 8 is a permutation -> conflict-free
__device__ __forceinline__ int pidx(int a) { return 5 * (a >> 2) + (a & 3); }

__device__ __forceinline__ float blockReduceSum(float v) {
    __shared__ float sh[32];
    int lane = threadIdx.x & 31, wid = threadIdx.x >> 5;
#pragma unroll
    for (int o = 16; o; o >>= 1) v += __shfl_xor_sync(0xffffffffu, v, o);
    __syncthreads();
    if (lane == 0) sh[wid] = v;
    __syncthreads();
    int nw = (blockDim.x + 31) >> 5;
    v = (lane < nw) ? sh[lane] : 0.f;
#pragma unroll
    for (int o = 16; o; o >>= 1) v += __shfl_xor_sync(0xffffffffu, v, o);
    return v;
}

// ---------------- single kernel: pair + struct + bond workers + polling finalizer ----------------
__global__ void __launch_bounds__(256)
mega_kernel(const float* __restrict__ xp, const float* __restrict__ xg,
            const float* __restrict__ sigma,
            const int* __restrict__ cond,
            const int* __restrict__ am, const int* __restrict__ om,
            const int* __restrict__ mol, const int* __restrict__ resid,
            const float* __restrict__ blen, const int* __restrict__ bidx,
            const int* __restrict__ bmask,
            float* __restrict__ out,
            int B, int T, int M, int NB,
            int ntiles, int tilepairs, int nPair, int nStruct, int nWorkers) {
    int blk = blockIdx.x;
    int tid = threadIdx.x;

    if (blk < nPair) {
        // ================= pair role: 32x32 atom tile, i<j upper triangle =================
        __shared__ ulonglong2          sAi[TT][40], sAj[TT][40];
        __shared__ unsigned long long  sBi[TT][40], sBj[TT][40];
        __shared__ float  s_tf[TT], s_fw[TT];
        __shared__ int    s_ri[32], s_rj[32];
        __shared__ float  s_vi[32], s_vj[32];
        __shared__ float  s_W;

        int b = blk / tilepairs;
        int p = blk % tilepairs;
        int ti = 0, rem = p;
        while (rem >= ntiles - ti) { rem -= ntiles - ti; ti++; }
        int tj = ti + rem;

        if (tid == 0) {
            float s = 0.f;
            for (int t = 0; t < TT; t++) {
                float tf = cond[b * TT + t] ? 0.f : 1.f;
                s_tf[t] = tf; s += tf;
            }
            float denom = fmaxf(s, 1.f);
            float W = 0.f;
            for (int t = 0; t < TT; t++) { float f = s_tf[t] / denom; s_fw[t] = f; W += f; }
            s_W = W;
        }

        for (int e = tid; e < TT * 32 * 3; e += 256) {
            int t = e / 96, r = e % 96, a = r / 3, d = r % 3;
            int gi = ti * 32 + a, gj = tj * 32 + a;
            long oi = (((long)(b * TT + t)) * M + gi) * 3 + d;
            long oj = (((long)(b * TT + t)) * M + gj) * 3 + d;
            int pa = pidx(a);
            float pi_ = xp[oi], gi_ = xg[oi];
            float pj_ = -xp[oj], gj_ = -xg[oj];
            if (d < 2) {
                ((float*)&sAi[t][pa])[2 * d + 0] = pi_;
                ((float*)&sAi[t][pa])[2 * d + 1] = gi_;
                ((float*)&sAj[t][pa])[2 * d + 0] = pj_;
                ((float*)&sAj[t][pa])[2 * d + 1] = gj_;
            } else {
                ((float*)&sBi[t][pa])[0] = pi_;
                ((float*)&sBi[t][pa])[1] = gi_;
                ((float*)&sBj[t][pa])[0] = pj_;
                ((float*)&sBj[t][pa])[1] = gj_;
            }
        }
        if (tid < 32) {
            int gi = ti * 32 + tid, gj = tj * 32 + tid;
            s_vi[tid] = (am[b * M + gi] && om[b * M + gi]) ? 1.f : 0.f;
            s_vj[tid] = (am[b * M + gj] && om[b * M + gj]) ? 1.f : 0.f;
            s_ri[tid] = resid[b * M + gi];
            s_rj[tid] = resid[b * M + gj];
        }
        __syncthreads();

        int ii = tid >> 3, jg = tid & 7;
        int gi = ti * 32 + ii;
        float vi = s_vi[ii];
        int   ri = s_ri[ii];
        int   ip = pidx(ii);
        int   jb = 5 * jg;          // pidx(jg*4+k) = 5*jg + k

        float lokf[4];
        bool  same[4];
#pragma unroll
        for (int k = 0; k < 4; k++) {
            int jj = jg * 4 + k, gj = tj * 32 + jj;
            bool vp = (gi < gj) && (vi != 0.f) && (s_vj[jj] != 0.f);
            lokf[k] = vp ? 1.f : 0.f;
            same[k] = vp && (ri == s_rj[jj]);
        }

        float sc = 0.f, cn = 0.f;
        // packed flex accumulators: e1=(Σfw·dp, Σfw·dg), e2=(Σfw·dp², Σfw·dg²)
        // e2 accumulates the packed squared-distance register directly (exact d²).
        unsigned long long e1a[4] = {0ull, 0ull, 0ull, 0ull};
        unsigned long long e2a[4] = {0ull, 0ull, 0ull, 0ull};

#pragma unroll
        for (int t = 0; t < TT; t++) {
            ulonglong2         Ai = sAi[t][ip];
            unsigned long long Bi = sBi[t][ip];
            float tf = s_tf[t], fw = s_fw[t];
            unsigned long long fw2; PACK2(fw2, fw, fw);
#pragma unroll
            for (int m = 0; m < 2; m++) {
                float nn[2], ddn[2];
#pragma unroll
                for (int q = 0; q < 2; q++) {
                    int k = 2 * m + q;
                    ulonglong2         Aj = sAj[t][jb + k];
                    unsigned long long Bj = sBj[t][jb + k];
                    unsigned long long dx, dy, dz, sq;
                    ADD2(dx, Ai.x, Aj.x);          // (dpx, dgx)
                    ADD2(dy, Ai.y, Aj.y);          // (dpy, dgy)
                    ADD2(dz, Bi,   Bj);            // (dpz, dgz)
                    MUL2(sq, dx, dx);
                    FMA2(sq, dy, dy, sq);
                    FMA2(sq, dz, dz, sq);          // (dp^2, dg^2), exact
                    float sqp, sqg; UNPACK2(sqp, sqg, sq);
                    float dp = fsqrt_approx(sqp);  // sq >= 0; i!=j distances never exactly 0
                    float dg = fsqrt_approx(sqg);

                    float diff = fminf(fabsf(dp - dg), 12.5f);
                    float x = __expf(diff);
                    float den = fmaf(fmaf(fmaf(fmaf(C_E4, x, C_E3), x, C_E2), x, C_E1), x, 1.f);
                    float num = fmaf(fmaf(fmaf(C_E3, x, C_N2), x, C_N1), x, 4.f);
                    float ok  = (dg < 15.f) ? lokf[k] * tf : 0.f;
                    nn[q]  = num * ok;
                    ddn[q] = den;
                    cn += ok;

                    // flex moments: e1 += fw*(dp,dg); e2 += fw*(dp²,dg²) from sq directly
                    unsigned long long dd;
                    PACK2(dd, dp, dg);
                    FMA2(e1a[k], fw2, dd, e1a[k]);
                    FMA2(e2a[k], fw2, sq, e2a[k]);
                }
                // one division per 2 pairs: n0/d0 + n1/d1 = (n0 d1 + n1 d0)/(d0 d1)
                float cross = fmaf(nn[1], ddn[0], nn[0] * ddn[1]);
                sc += __fdividef(cross, ddn[0] * ddn[1]);
            }
        }

#pragma unroll
        for (int k = 0; k < 4; k++) {
            if (same[k]) {
                float e1p, e1g, e2p, e2g;
                UNPACK2(e1p, e1g, e1a[k]);
                UNPACK2(e2p, e2g, e2a[k]);
                float W = s_W;
                float vp_ = fmaxf(e2p - e1p * e1p * (2.f - W), 0.f);
                float vg_ = fmaxf(e2g - e1g * e1g * (2.f - W), 0.f);
                float sp = fsqrt_approx(vp_ + 1e-8f);
                float sg = fsqrt_approx(vg_ + 1e-8f);
                float dq = (sp - sg) * (sp - sg);
                int r = min(max(ri, 0), NRES - 1);
                atomicAdd(&g_res_sum[b * NRES + r], dq);
                atomicAdd(&g_res_cnt[b * NRES + r], 1.f);
            }
        }

        float tsc = blockReduceSum(sc);
        float tcn = blockReduceSum(cn);
        if (tid == 0) {
            atomicAdd(&g_lddt_score, (double)tsc);
            atomicAdd(&g_lddt_cnt, (double)tcn);
        }
        // publish: release-red (write-side only; no L1 invalidate)
        __syncthreads();
        if (tid == 0) red_release_add(&g_done, 1u);
    } else if (blk < nPair + nStruct) {
        // ================= struct role: one block per (b,t); also counts valid atoms =================
        int bt = blk - nPair;
        int b = bt / T;
        const float* P = xp + (long)bt * M * 3;
        const float* G = xg + (long)bt * M * 3;
        float acc = 0.f, vcnt = 0.f;
        for (int m = tid; m < M; m += 256) {
            float d0 = P[m * 3 + 0] - G[m * 3 + 0];
            float d1 = P[m * 3 + 1] - G[m * 3 + 1];
            float d2 = P[m * 3 + 2] - G[m * 3 + 2];
            float sq = fmaf(d0, d0, fmaf(d1, d1, d2 * d2));
            bool v = am[b * M + m] && om[b * M + m];
            int mt = mol[b * M + m];
            float w = v ? ((mt == 0) ? 1.f : (mt == 3) ? 10.f : 5.f) : 0.f;
            acc += sq * w;
            vcnt += v ? 1.f : 0.f;
        }
        acc  = blockReduceSum(acc);
        vcnt = blockReduceSum(vcnt);
        if (tid == 0) __stcg(&g_struct_pf[bt], acc / fmaxf(vcnt, 1.f));   // L2 direct
        __syncthreads();
        if (tid == 0) red_release_add(&g_done, 1u);
    } else if (blk < nWorkers) {
        // ================= bond role: one thread per (b, bond, frame) =================
        int g = (blk - nPair - nStruct) * 256 + tid;
        float num = 0.f, den = 0.f;
        if (g < B * NB * T) {
            int b  = g / (NB * T);
            int r  = g % (NB * T);
            int nb = r / T;
            int t  = r % T;
            int bond = b * NB + nb;
            if (bmask[bond]) {
                float tf = cond[b * T + t] ? 0.f : 1.f;
                int i = bidx[bond * 2 + 0];
                int j = bidx[bond * 2 + 1];
                const float* base = xp + ((long)(b * T + t)) * M * 3;
                float d0 = base[i * 3 + 0] - base[j * 3 + 0];
                float d1 = base[i * 3 + 1] - base[j * 3 + 1];
                float d2 = base[i * 3 + 2] - base[j * 3 + 2];
                float pl = fsqrt_approx(fmaf(d0, d0, fmaf(d1, d1, d2 * d2)) + 1e-12f);
                float df = pl - blen[bond];
                num = df * df * tf;
                den = tf;
            }
        }
        num = blockReduceSum(num);
        den = blockReduceSum(den);
        if (tid == 0) {
            atomicAdd(&g_bond_num, (double)num);
            atomicAdd(&g_bond_den, (double)den);
        }
        __syncthreads();
        if (tid == 0) red_release_add(&g_done, 1u);
    } else {
        // ================= finalizer block: poll L2 counter, then reduce =================
        __shared__ unsigned int s_go;
        if (tid == 0) {
            while (ldcg_u32(&g_done) < (unsigned int)nWorkers) __nanosleep(64);
            s_go = 1u;
        }
        __syncthreads();
        (void)s_go;

        // all accumulator state is in L2 (atomics / st.cg); read via __ldcg
        float lsum = 0.f, lok2 = 0.f;
        for (int i = tid; i < B * NRES; i += 256) {
            float c = __ldcg(&g_res_cnt[i]);
            if (c > 0.f) { lsum += __ldcg(&g_res_sum[i]) / c; lok2 += 1.f; }
        }
        float t1 = blockReduceSum(lsum);
        float t2 = blockReduceSum(lok2);

        float ssum = 0.f, tfs = 0.f;
        for (int i = tid; i < B * T; i += 256) {
            float s = sigma[i];
            float tf = cond[i] ? 0.f : 1.f;
            tfs += tf;
            float den = s * 16.f + 1e-8f;
            float ew = (s * s + 256.f) / (den * den) * tf;
            ssum += ew * __ldcg(&g_struct_pf[i]);
        }
        float t3 = blockReduceSum(ssum);
        float t4 = blockReduceSum(tfs);

        if (tid == 0) {
            double lsc  = __longlong_as_double(__ldcg((const long long*)&g_lddt_score));
            double lcn  = __longlong_as_double(__ldcg((const long long*)&g_lddt_cnt));
            double bnum = __longlong_as_double(__ldcg((const long long*)&g_bond_num));
            double bden = __longlong_as_double(__ldcg((const long long*)&g_bond_den));
            float l_local  = t1 / fmaxf(t2, 1.f);
            float l_struct = t3 / fmaxf(t4, 1.f);
            float l_lddt = 1.f - (float)((lsc * 0.25) / (lcn > 1.0 ? lcn : 1.0));
            float l_bond = (float)(bnum / (bden > 1.0 ? bden : 1.0));
            out[0] = l_struct + l_bond + l_lddt + 4.f * l_local;
        }

        // restore all-zero invariant (kernel-completion boundary publishes to next call)
        __syncthreads();
        for (int i = tid; i < 8 * NRES; i += 256) { g_res_sum[i] = 0.f; g_res_cnt[i] = 0.f; }
        for (int i = tid; i < 64; i += 256)        { g_struct_pf[i] = 0.f; }
        if (tid == 0) {
            g_lddt_score = 0.0; g_lddt_cnt = 0.0;
            g_bond_num = 0.0;   g_bond_den = 0.0;
            g_done = 0u;
        }
    }
}

// ---------------- launch ----------------
extern "C" void kernel_launch(void* const* d_in, const int* in_sizes, int n_in,
                              void* d_out, int out_size) {
    const float* xp    = (const float*)d_in[0];
    const float* xg    = (const float*)d_in[1];
    const float* sigma = (const float*)d_in[2];
    const float* blen  = (const float*)d_in[3];
    const int*   cond  = (const int*)d_in[4];
    const int*   am    = (const int*)d_in[5];
    const int*   om    = (const int*)d_in[6];
    const int*   mol   = (const int*)d_in[7];
    const int*   resid = (const int*)d_in[8];
    const int*   bidx  = (const int*)d_in[9];
    const int*   bmask = (const int*)d_in[10];

    int BT = in_sizes[2];                 // B*T
    int M  = in_sizes[0] / (BT * 3);      // atoms
    int B  = in_sizes[5] / M;             // batch
    int T  = BT / B;                      // frames (== 8)
    int NB = in_sizes[10] / B;            // bonds

    int ntiles = M / 32;
    int tilepairs = ntiles * (ntiles + 1) / 2;
    int nPair    = B * tilepairs;
    int nStruct  = B * T;
    int nBond    = (B * NB * T + 255) / 256;
    int nWorkers = nPair + nStruct + nBond;
    mega_kernel<<<nWorkers + 1, 256>>>(
        xp, xg, sigma, cond, am, om, mol, resid, blen, bidx, bmask,
        (float*)d_out, B, T, M, NB, ntiles, tilepairs, nPair, nStruct, nWorkers);
}